// round 2
// baseline (speedup 1.0000x reference)
#include <cuda_runtime.h>
#include <cuda_bf16.h>
#include <math.h>

using bf16 = __nv_bfloat16;

#define DIVUP(a,b) (((a)+(b)-1)/(b))

// Problem dims
constexpr int Bn = 32;       // batch
constexpr int Cc = 512;      // channels
constexpr int Ss = 1024;     // H*W sequence
constexpr int GROUPS = 32;
constexpr int CG = Cc / GROUPS;   // 16 channels per group

// ---------------- scratch (static device allocations) ----------------
__device__ bf16  g_norm[(size_t)Bn * Ss * Cc];     // [B*S, C]  32MB
__device__ bf16  g_q   [(size_t)Bn * Ss * Cc];     // [B*S, C]  (pre-scaled)
__device__ bf16  g_k   [(size_t)Bn * Ss * Cc];     // [B*S, C]
__device__ bf16  g_vT  [(size_t)Bn * Cc * Ss];     // [B, C, S] transposed
__device__ float g_scores[(size_t)Bn * Ss * Ss];   // [B, S, S] 128MB
__device__ bf16  g_p   [(size_t)Bn * Ss * Ss];     // softmax probs 64MB
__device__ bf16  g_ao  [(size_t)Bn * Ss * Cc];     // attn out [B*S, C]
__device__ bf16  g_wqkv[3 * Cc * Cc];
__device__ bf16  g_wout[Cc * Cc];

// ---------------- small kernels ----------------
__global__ void cvt_kernel(const float* __restrict__ in, int n, int which) {
    int i = blockIdx.x * 256 + threadIdx.x;
    if (i < n) {
        bf16 v = __float2bfloat16(in[i]);
        if (which == 0) g_wqkv[i] = v; else g_wout[i] = v;
    }
}

// GroupNorm + transpose to [B,S,C] bf16.
// One block per (batch, group). Group data is a contiguous 16384-float chunk.
__global__ void __launch_bounds__(256) groupnorm_kernel(
    const float* __restrict__ x, const float* __restrict__ gamma,
    const float* __restrict__ beta)
{
    int bg  = blockIdx.x;
    int b   = bg >> 5;
    int grp = bg & 31;
    const float* base = x + ((size_t)(b * Cc + grp * CG)) * Ss;
    int tid = threadIdx.x;

    // phase 1: sum / sumsq over 16384 elements (coalesced float4)
    float s = 0.f, ss = 0.f;
    const float4* base4 = (const float4*)base;
    #pragma unroll
    for (int i = 0; i < 16; i++) {
        float4 v = base4[tid + i * 256];
        s  += v.x + v.y + v.z + v.w;
        ss += v.x * v.x + v.y * v.y + v.z * v.z + v.w * v.w;
    }
    __shared__ float wsum[8], wsq[8];
    __shared__ float s_mean, s_rstd;
    #pragma unroll
    for (int o = 16; o; o >>= 1) {
        s  += __shfl_xor_sync(0xffffffffu, s, o);
        ss += __shfl_xor_sync(0xffffffffu, ss, o);
    }
    if ((tid & 31) == 0) { wsum[tid >> 5] = s; wsq[tid >> 5] = ss; }
    __syncthreads();
    if (tid == 0) {
        float S = 0.f, SS = 0.f;
        #pragma unroll
        for (int i = 0; i < 8; i++) { S += wsum[i]; SS += wsq[i]; }
        float mean = S * (1.f / 16384.f);
        float var  = SS * (1.f / 16384.f) - mean * mean;
        s_mean = mean;
        s_rstd = rsqrtf(var + 1e-5f);
    }
    __syncthreads();
    float mean = s_mean, rstd = s_rstd;

    // phase 2: normalize + transpose write.
    // thread -> 4 consecutive channels, 64 s-values (8B bf16 stores, coalesced)
    int c4   = (tid & 3) * 4;
    int srow = tid >> 2;             // 0..63
    float ga[4], be[4];
    #pragma unroll
    for (int cc = 0; cc < 4; cc++) {
        int c = grp * CG + c4 + cc;
        ga[cc] = gamma[c]; be[cc] = beta[c];
    }
    #pragma unroll
    for (int j = 0; j < 16; j++) {
        int sI = j * 64 + srow;
        float v[4];
        #pragma unroll
        for (int cc = 0; cc < 4; cc++)
            v[cc] = (base[(size_t)(c4 + cc) * Ss + sI] - mean) * rstd * ga[cc] + be[cc];
        __nv_bfloat162 p0 = __floats2bfloat162_rn(v[0], v[1]);
        __nv_bfloat162 p1 = __floats2bfloat162_rn(v[2], v[3]);
        union { __nv_bfloat162 h2[2]; uint2 u; } pk;
        pk.h2[0] = p0; pk.h2[1] = p1;
        *(uint2*)(g_norm + ((size_t)(b * Ss + sI)) * Cc + grp * CG + c4) = pk.u;
    }
}

// Row softmax: fp32 scores -> bf16 probs. One block per row (1024 cols).
__global__ void __launch_bounds__(256) softmax_kernel() {
    size_t row = blockIdx.x;
    int tid = threadIdx.x;
    const float4 v = ((const float4*)(g_scores + row * Ss))[tid];
    float m = fmaxf(fmaxf(v.x, v.y), fmaxf(v.z, v.w));
    __shared__ float smax[8], ssum[8];
    #pragma unroll
    for (int o = 16; o; o >>= 1) m = fmaxf(m, __shfl_xor_sync(0xffffffffu, m, o));
    if ((tid & 31) == 0) smax[tid >> 5] = m;
    __syncthreads();
    float M = smax[0];
    #pragma unroll
    for (int i = 1; i < 8; i++) M = fmaxf(M, smax[i]);
    float e0 = __expf(v.x - M), e1 = __expf(v.y - M);
    float e2 = __expf(v.z - M), e3 = __expf(v.w - M);
    float s = e0 + e1 + e2 + e3;
    #pragma unroll
    for (int o = 16; o; o >>= 1) s += __shfl_xor_sync(0xffffffffu, s, o);
    if ((tid & 31) == 0) ssum[tid >> 5] = s;
    __syncthreads();
    float S = 0.f;
    #pragma unroll
    for (int i = 0; i < 8; i++) S += ssum[i];
    float inv = 1.f / S;
    union { __nv_bfloat162 h2[2]; uint2 u; } pk;
    pk.h2[0] = __floats2bfloat162_rn(e0 * inv, e1 * inv);
    pk.h2[1] = __floats2bfloat162_rn(e2 * inv, e3 * inv);
    *(uint2*)(g_p + row * Ss + tid * 4) = pk.u;
}

// ---------------- bf16 NT GEMM core (mma.sync m16n8k16) ----------------
// C[M,N] = A[M,K] * B[N,K]^T, both K-contiguous. BM=128 BN=64 BK=32.
// 256 threads = 8 warps in 4(m) x 2(n); warp tile 32x32 = 2x4 m16n8 mmas.
constexpr int BM = 128, BN = 64, BK = 32, TLD = 40;  // 40 = conflict-free frag LDS

__device__ __forceinline__ void mma_bf16(float* d, const unsigned* a, const unsigned* b) {
    asm volatile(
        "mma.sync.aligned.m16n8k16.row.col.f32.bf16.bf16.f32 "
        "{%0,%1,%2,%3}, {%4,%5,%6,%7}, {%8,%9}, {%0,%1,%2,%3};\n"
        : "+f"(d[0]), "+f"(d[1]), "+f"(d[2]), "+f"(d[3])
        : "r"(a[0]), "r"(a[1]), "r"(a[2]), "r"(a[3]), "r"(b[0]), "r"(b[1]));
}

__device__ __forceinline__ void gemm_core(
    const bf16* __restrict__ A, const bf16* __restrict__ B, int K,
    float (&acc)[2][4][4], bf16* As, bf16* Bs)
{
    int tid  = threadIdx.x;
    int warp = tid >> 5, lane = tid & 31;
    int wm = warp >> 1, wn = warp & 1;
    int g = lane >> 2, tg = lane & 3;
    int arow = tid >> 2;             // 0..63
    int acol = (tid & 3) * 8;        // 0,8,16,24 (bf16 elems)

    for (int k0 = 0; k0 < K; k0 += BK) {
        uint4 a0 = *(const uint4*)(A + (size_t)arow * K        + k0 + acol);
        uint4 a1 = *(const uint4*)(A + (size_t)(arow + 64) * K + k0 + acol);
        uint4 b0 = *(const uint4*)(B + (size_t)arow * K        + k0 + acol);
        __syncthreads();
        *(uint4*)(As + arow * TLD + acol)        = a0;
        *(uint4*)(As + (arow + 64) * TLD + acol) = a1;
        *(uint4*)(Bs + arow * TLD + acol)        = b0;
        __syncthreads();
        #pragma unroll
        for (int kk = 0; kk < BK; kk += 16) {
            unsigned af[2][4], bfr[4][2];
            #pragma unroll
            for (int i = 0; i < 2; i++) {
                const bf16* p0 = As + (wm * 32 + i * 16 + g)     * TLD + kk + 2 * tg;
                const bf16* p1 = As + (wm * 32 + i * 16 + g + 8) * TLD + kk + 2 * tg;
                af[i][0] = *(const unsigned*)p0;
                af[i][1] = *(const unsigned*)p1;
                af[i][2] = *(const unsigned*)(p0 + 8);
                af[i][3] = *(const unsigned*)(p1 + 8);
            }
            #pragma unroll
            for (int j = 0; j < 4; j++) {
                const bf16* q0 = Bs + (wn * 32 + j * 8 + g) * TLD + kk + 2 * tg;
                bfr[j][0] = *(const unsigned*)q0;
                bfr[j][1] = *(const unsigned*)(q0 + 8);
            }
            #pragma unroll
            for (int i = 0; i < 2; i++)
                #pragma unroll
                for (int j = 0; j < 4; j++)
                    mma_bf16(acc[i][j], af[i], bfr[j]);
        }
    }
}

// acc element -> (row, col): c0=(g,2t) c1=(g,2t+1) c2=(g+8,2t) c3=(g+8,2t+1)
#define EPILOGUE_COORDS                                            \
    int tid  = threadIdx.x;                                        \
    int warp = tid >> 5, lane = tid & 31;                          \
    int wm = warp >> 1, wn = warp & 1;                             \
    int g = lane >> 2, tg = lane & 3;

// ---------------- GEMM specializations ----------------
// QKV: [32768,1536] = norm[32768,512] @ wqkv[1536,512]^T  (+bias; route q/k/vT)
__global__ void __launch_bounds__(256) qkv_kernel(const float* __restrict__ b_qkv) {
    __shared__ bf16 As[BM * TLD];
    __shared__ bf16 Bs[BN * TLD];
    int bm = blockIdx.y * BM;
    int bn = blockIdx.x * BN;
    float acc[2][4][4] = {};
    gemm_core(g_norm + (size_t)bm * Cc, g_wqkv + (size_t)bn * Cc, Cc, acc, As, Bs);
    EPILOGUE_COORDS;
    const float scale = 0.044194173824159216f;   // 1/sqrt(512)
    int seg = bn >> 9;                            // 0=q 1=k 2=v (tile fully inside)
    #pragma unroll
    for (int i = 0; i < 2; i++)
        #pragma unroll
        for (int half = 0; half < 2; half++) {
            int r = bm + wm * 32 + i * 16 + g + half * 8;
            #pragma unroll
            for (int j = 0; j < 4; j++) {
                int c = bn + wn * 32 + j * 8 + 2 * tg;
                float v0 = acc[i][j][half * 2 + 0] + b_qkv[c];
                float v1 = acc[i][j][half * 2 + 1] + b_qkv[c + 1];
                if (seg == 0) {
                    *(__nv_bfloat162*)(g_q + (size_t)r * Cc + c) =
                        __floats2bfloat162_rn(v0 * scale, v1 * scale);
                } else if (seg == 1) {
                    *(__nv_bfloat162*)(g_k + (size_t)r * Cc + (c - 512)) =
                        __floats2bfloat162_rn(v0, v1);
                } else {
                    int bb = r >> 10, sI = r & 1023;
                    g_vT[((size_t)(bb * Cc + (c - 1024))) * Ss + sI] = __float2bfloat16(v0);
                    g_vT[((size_t)(bb * Cc + (c - 1023))) * Ss + sI] = __float2bfloat16(v1);
                }
            }
        }
}

// QK^T: per batch [1024,1024] = q[1024,512] @ k[1024,512]^T -> fp32 scores
__global__ void __launch_bounds__(256) qk_kernel() {
    __shared__ bf16 As[BM * TLD];
    __shared__ bf16 Bs[BN * TLD];
    int z = blockIdx.z;
    int bm = blockIdx.y * BM, bn = blockIdx.x * BN;
    float acc[2][4][4] = {};
    gemm_core(g_q + ((size_t)z * Ss + bm) * Cc,
              g_k + ((size_t)z * Ss + bn) * Cc, Cc, acc, As, Bs);
    EPILOGUE_COORDS;
    float* outp = g_scores + (size_t)z * Ss * Ss;
    #pragma unroll
    for (int i = 0; i < 2; i++)
        #pragma unroll
        for (int half = 0; half < 2; half++) {
            int r = bm + wm * 32 + i * 16 + g + half * 8;
            #pragma unroll
            for (int j = 0; j < 4; j++) {
                int c = bn + wn * 32 + j * 8 + 2 * tg;
                *(float2*)(outp + (size_t)r * Ss + c) =
                    make_float2(acc[i][j][half * 2], acc[i][j][half * 2 + 1]);
            }
        }
}

// PV: per batch [1024,512] = p[1024,1024] @ vT[512,1024]^T -> bf16 attn out
__global__ void __launch_bounds__(256) pv_kernel() {
    __shared__ bf16 As[BM * TLD];
    __shared__ bf16 Bs[BN * TLD];
    int z = blockIdx.z;
    int bm = blockIdx.y * BM, bn = blockIdx.x * BN;
    float acc[2][4][4] = {};
    gemm_core(g_p  + (size_t)z * Ss * Ss + (size_t)bm * Ss,
              g_vT + ((size_t)z * Cc + bn) * Ss, Ss, acc, As, Bs);
    EPILOGUE_COORDS;
    #pragma unroll
    for (int i = 0; i < 2; i++)
        #pragma unroll
        for (int half = 0; half < 2; half++) {
            int r = bm + wm * 32 + i * 16 + g + half * 8;
            #pragma unroll
            for (int j = 0; j < 4; j++) {
                int c = bn + wn * 32 + j * 8 + 2 * tg;
                *(__nv_bfloat162*)(g_ao + ((size_t)z * Ss + r) * Cc + c) =
                    __floats2bfloat162_rn(acc[i][j][half * 2], acc[i][j][half * 2 + 1]);
            }
        }
}

// Out proj: per batch C[o=512, s=1024] = wout[512,512] @ ao[1024,512]^T
// epilogue: + b_out[o] + x[b,o,s] -> d_out fp32 (coalesced along s)
__global__ void __launch_bounds__(256) out_kernel(
    const float* __restrict__ b_out, const float* __restrict__ x,
    float* __restrict__ out)
{
    __shared__ bf16 As[BM * TLD];
    __shared__ bf16 Bs[BN * TLD];
    int z = blockIdx.z;
    int bm = blockIdx.y * BM, bn = blockIdx.x * BN;
    float acc[2][4][4] = {};
    gemm_core(g_wout + (size_t)bm * Cc,
              g_ao + ((size_t)z * Ss + bn) * Cc, Cc, acc, As, Bs);
    EPILOGUE_COORDS;
    #pragma unroll
    for (int i = 0; i < 2; i++)
        #pragma unroll
        for (int half = 0; half < 2; half++) {
            int r = bm + wm * 32 + i * 16 + g + half * 8;   // channel o
            float bias = b_out[r];
            #pragma unroll
            for (int j = 0; j < 4; j++) {
                int c = bn + wn * 32 + j * 8 + 2 * tg;      // spatial s
                size_t off = ((size_t)(z * Cc + r)) * Ss + c;
                float2 xv = *(const float2*)(x + off);
                float2 ov;
                ov.x = acc[i][j][half * 2 + 0] + bias + xv.x;
                ov.y = acc[i][j][half * 2 + 1] + bias + xv.y;
                *(float2*)(out + off) = ov;
            }
        }
}

// ---------------- launcher ----------------
extern "C" void kernel_launch(void* const* d_in, const int* in_sizes, int n_in,
                              void* d_out, int out_size)
{
    const float* x     = (const float*)d_in[0];
    const float* gamma = (const float*)d_in[1];
    const float* beta  = (const float*)d_in[2];
    const float* w_qkv = (const float*)d_in[3];
    const float* b_qkv = (const float*)d_in[4];
    const float* w_out = (const float*)d_in[5];
    const float* b_out = (const float*)d_in[6];
    float* out = (float*)d_out;

    cvt_kernel<<<DIVUP(3 * Cc * Cc, 256), 256>>>(w_qkv, 3 * Cc * Cc, 0);
    cvt_kernel<<<DIVUP(Cc * Cc, 256), 256>>>(w_out, Cc * Cc, 1);
    groupnorm_kernel<<<Bn * GROUPS, 256>>>(x, gamma, beta);
    qkv_kernel<<<dim3(3 * Cc / BN, Bn * Ss / BM), 256>>>(b_qkv);
    qk_kernel<<<dim3(Ss / BN, Ss / BM, Bn), 256>>>();
    softmax_kernel<<<Bn * Ss, 256>>>();
    pv_kernel<<<dim3(Cc / BN, Ss / BM, Bn), 256>>>();
    out_kernel<<<dim3(Ss / BN, Cc / BM, Bn), 256>>>(b_out, x, out);
}

// round 3
// speedup vs baseline: 1.4066x; 1.4066x over previous
#include <cuda_runtime.h>
#include <cuda_bf16.h>
#include <math.h>

using bf16 = __nv_bfloat16;

#define DIVUP(a,b) (((a)+(b)-1)/(b))

// Problem dims
constexpr int Bn = 32;       // batch
constexpr int Cc = 512;      // channels
constexpr int Ss = 1024;     // H*W sequence
constexpr int GROUPS = 32;
constexpr int CG = Cc / GROUPS;   // 16

// ---------------- scratch ----------------
__device__ bf16  g_norm[(size_t)Bn * Ss * Cc];     // [B*S, C]
__device__ bf16  g_q   [(size_t)Bn * Ss * Cc];     // [B*S, C] (pre-scaled)
__device__ bf16  g_k   [(size_t)Bn * Ss * Cc];     // [B*S, C]
__device__ bf16  g_vT  [(size_t)Bn * Cc * Ss];     // [B, C, S]
__device__ bf16  g_scores[(size_t)Bn * Ss * Ss];   // scores -> probs in place (64MB)
__device__ bf16  g_ao  [(size_t)Bn * Ss * Cc];     // attn out [B*S, C]
__device__ bf16  g_wqkv[3 * Cc * Cc];
__device__ bf16  g_wout[Cc * Cc];

// ---------------- small kernels ----------------
__global__ void cvt_kernel(const float* __restrict__ in, int n, int which) {
    int i = blockIdx.x * 256 + threadIdx.x;
    if (i < n) {
        bf16 v = __float2bfloat16(in[i]);
        if (which == 0) g_wqkv[i] = v; else g_wout[i] = v;
    }
}

// GroupNorm + transpose to [B,S,C] bf16. One block per (batch, group).
__global__ void __launch_bounds__(256) groupnorm_kernel(
    const float* __restrict__ x, const float* __restrict__ gamma,
    const float* __restrict__ beta)
{
    int bg  = blockIdx.x;
    int b   = bg >> 5;
    int grp = bg & 31;
    const float* base = x + ((size_t)(b * Cc + grp * CG)) * Ss;
    int tid = threadIdx.x;

    float s = 0.f, ss = 0.f;
    const float4* base4 = (const float4*)base;
    #pragma unroll
    for (int i = 0; i < 16; i++) {
        float4 v = base4[tid + i * 256];
        s  += v.x + v.y + v.z + v.w;
        ss += v.x * v.x + v.y * v.y + v.z * v.z + v.w * v.w;
    }
    __shared__ float wsum[8], wsq[8];
    __shared__ float s_mean, s_rstd;
    #pragma unroll
    for (int o = 16; o; o >>= 1) {
        s  += __shfl_xor_sync(0xffffffffu, s, o);
        ss += __shfl_xor_sync(0xffffffffu, ss, o);
    }
    if ((tid & 31) == 0) { wsum[tid >> 5] = s; wsq[tid >> 5] = ss; }
    __syncthreads();
    if (tid == 0) {
        float S = 0.f, SS = 0.f;
        #pragma unroll
        for (int i = 0; i < 8; i++) { S += wsum[i]; SS += wsq[i]; }
        float mean = S * (1.f / 16384.f);
        float var  = SS * (1.f / 16384.f) - mean * mean;
        s_mean = mean;
        s_rstd = rsqrtf(var + 1e-5f);
    }
    __syncthreads();
    float mean = s_mean, rstd = s_rstd;

    int c4   = (tid & 3) * 4;
    int srow = tid >> 2;
    float ga[4], be[4];
    #pragma unroll
    for (int cc = 0; cc < 4; cc++) {
        int c = grp * CG + c4 + cc;
        ga[cc] = gamma[c]; be[cc] = beta[c];
    }
    #pragma unroll
    for (int j = 0; j < 16; j++) {
        int sI = j * 64 + srow;
        float v[4];
        #pragma unroll
        for (int cc = 0; cc < 4; cc++)
            v[cc] = (base[(size_t)(c4 + cc) * Ss + sI] - mean) * rstd * ga[cc] + be[cc];
        union { __nv_bfloat162 h2[2]; uint2 u; } pk;
        pk.h2[0] = __floats2bfloat162_rn(v[0], v[1]);
        pk.h2[1] = __floats2bfloat162_rn(v[2], v[3]);
        *(uint2*)(g_norm + ((size_t)(b * Ss + sI)) * Cc + grp * CG + c4) = pk.u;
    }
}

// Row softmax in place over bf16 scores. One block per row (1024 cols).
__global__ void __launch_bounds__(256) softmax_kernel() {
    size_t row = blockIdx.x;
    int tid = threadIdx.x;
    uint2 raw = ((const uint2*)(g_scores + row * Ss))[tid];
    __nv_bfloat162 h0 = *(__nv_bfloat162*)&raw.x;
    __nv_bfloat162 h1 = *(__nv_bfloat162*)&raw.y;
    float v0 = __bfloat162float(h0.x), v1 = __bfloat162float(h0.y);
    float v2 = __bfloat162float(h1.x), v3 = __bfloat162float(h1.y);
    float m = fmaxf(fmaxf(v0, v1), fmaxf(v2, v3));
    __shared__ float smax[8], ssum[8];
    #pragma unroll
    for (int o = 16; o; o >>= 1) m = fmaxf(m, __shfl_xor_sync(0xffffffffu, m, o));
    if ((tid & 31) == 0) smax[tid >> 5] = m;
    __syncthreads();
    float M = smax[0];
    #pragma unroll
    for (int i = 1; i < 8; i++) M = fmaxf(M, smax[i]);
    float e0 = __expf(v0 - M), e1 = __expf(v1 - M);
    float e2 = __expf(v2 - M), e3 = __expf(v3 - M);
    float s = e0 + e1 + e2 + e3;
    #pragma unroll
    for (int o = 16; o; o >>= 1) s += __shfl_xor_sync(0xffffffffu, s, o);
    if ((tid & 31) == 0) ssum[tid >> 5] = s;
    __syncthreads();
    float S = 0.f;
    #pragma unroll
    for (int i = 0; i < 8; i++) S += ssum[i];
    float inv = 1.f / S;
    union { __nv_bfloat162 h2[2]; uint2 u; } pk;
    pk.h2[0] = __floats2bfloat162_rn(e0 * inv, e1 * inv);
    pk.h2[1] = __floats2bfloat162_rn(e2 * inv, e3 * inv);
    *(uint2*)(g_scores + row * Ss + tid * 4) = pk.u;
}

// ---------------- pipelined bf16 NT GEMM core ----------------
// C[M,N] = A[M,K] * B[N,K]^T, K-contiguous. BM=128 BN=128 BK=32, 2-stage cp.async.
// 256 threads = 8 warps (4m x 2n); warp tile 32x64 = 2x8 m16n8k16 mmas.
// TLD=40 element row stride: conflict-free for both STS.128 and ldmatrix.
constexpr int BM = 128, BN = 128, BK = 32, TLD = 40;

__device__ __forceinline__ unsigned sptr(const void* p) {
    return (unsigned)__cvta_generic_to_shared(p);
}
__device__ __forceinline__ void cp16(bf16* dst, const bf16* src) {
    asm volatile("cp.async.cg.shared.global [%0], [%1], 16;"
                 :: "r"(sptr(dst)), "l"(src));
}
__device__ __forceinline__ void cp_commit() {
    asm volatile("cp.async.commit_group;");
}
template<int N> __device__ __forceinline__ void cp_wait() {
    asm volatile("cp.async.wait_group %0;" :: "n"(N));
}
__device__ __forceinline__ void ldsm4(unsigned& r0, unsigned& r1, unsigned& r2,
                                      unsigned& r3, const bf16* p) {
    asm volatile("ldmatrix.sync.aligned.m8n8.x4.shared.b16 {%0,%1,%2,%3}, [%4];"
                 : "=r"(r0), "=r"(r1), "=r"(r2), "=r"(r3) : "r"(sptr(p)));
}
__device__ __forceinline__ void mma_bf16(float* d, const unsigned* a, const unsigned* b) {
    asm volatile(
        "mma.sync.aligned.m16n8k16.row.col.f32.bf16.bf16.f32 "
        "{%0,%1,%2,%3}, {%4,%5,%6,%7}, {%8,%9}, {%0,%1,%2,%3};\n"
        : "+f"(d[0]), "+f"(d[1]), "+f"(d[2]), "+f"(d[3])
        : "r"(a[0]), "r"(a[1]), "r"(a[2]), "r"(a[3]), "r"(b[0]), "r"(b[1]));
}

__device__ __forceinline__ void load_stage(
    const bf16* __restrict__ A, const bf16* __restrict__ B, int K, int k0,
    bf16* As, bf16* Bs, int tid)
{
    #pragma unroll
    for (int t = 0; t < 2; t++) {
        int ch  = tid + t * 256;          // 0..511
        int row = ch >> 2;
        int c   = (ch & 3) * 8;
        cp16(As + row * TLD + c, A + (size_t)row * K + k0 + c);
        cp16(Bs + row * TLD + c, B + (size_t)row * K + k0 + c);
    }
}

__device__ __forceinline__ void compute_stage(
    const bf16* As, const bf16* Bs, float (&acc)[2][8][4], int wm, int wn, int lane)
{
    #pragma unroll
    for (int kk = 0; kk < BK; kk += 16) {
        unsigned a[2][4], b[8][2];
        #pragma unroll
        for (int i = 0; i < 2; i++) {
            const bf16* p = As + (wm * 32 + i * 16 + (lane & 15)) * TLD
                          + kk + ((lane >> 4) << 3);
            ldsm4(a[i][0], a[i][1], a[i][2], a[i][3], p);
        }
        #pragma unroll
        for (int jj = 0; jj < 4; jj++) {
            const bf16* p = Bs + (wn * 64 + jj * 16 + ((lane >> 4) << 3) + (lane & 7)) * TLD
                          + kk + (((lane >> 3) & 1) << 3);
            unsigned r0, r1, r2, r3;
            ldsm4(r0, r1, r2, r3, p);
            b[2 * jj][0] = r0;     b[2 * jj][1] = r1;
            b[2 * jj + 1][0] = r2; b[2 * jj + 1][1] = r3;
        }
        #pragma unroll
        for (int i = 0; i < 2; i++)
            #pragma unroll
            for (int j = 0; j < 8; j++)
                mma_bf16(acc[i][j], a[i], b[j]);
    }
}

__device__ __forceinline__ void gemm_core(
    const bf16* __restrict__ A, const bf16* __restrict__ B, int K,
    float (&acc)[2][8][4], bf16 (*As)[BM * TLD], bf16 (*Bs)[BN * TLD])
{
    int tid  = threadIdx.x;
    int lane = tid & 31, warp = tid >> 5;
    int wm = warp >> 1, wn = warp & 1;
    int nk = K / BK;

    load_stage(A, B, K, 0, As[0], Bs[0], tid);
    cp_commit();
    for (int k0 = 0; k0 < nk; k0++) {
        if (k0 + 1 < nk) {
            load_stage(A, B, K, (k0 + 1) * BK, As[(k0 + 1) & 1], Bs[(k0 + 1) & 1], tid);
            cp_commit();
            cp_wait<1>();
        } else {
            cp_wait<0>();
        }
        __syncthreads();
        compute_stage(As[k0 & 1], Bs[k0 & 1], acc, wm, wn, lane);
        __syncthreads();
    }
}

// acc[i][j][c]: row = bm + wm*32 + i*16 + g + (c>=2?8:0); col = bn + wn*64 + j*8 + 2*tg + (c&1)
#define EPILOGUE_COORDS                                            \
    int tid  = threadIdx.x;                                        \
    int warp = tid >> 5, lane = tid & 31;                          \
    int wm = warp >> 1, wn = warp & 1;                             \
    int g = lane >> 2, tg = lane & 3;

#define GEMM_SMEM                                                  \
    __shared__ bf16 As[2][BM * TLD];                               \
    __shared__ bf16 Bs[2][BN * TLD];

// ---------------- GEMM specializations ----------------
// QKV: [32768,1536] = norm @ wqkv^T (+bias; route q/k/vT)
__global__ void __launch_bounds__(256) qkv_kernel(const float* __restrict__ b_qkv) {
    GEMM_SMEM;
    int bm = blockIdx.y * BM;
    int bn = blockIdx.x * BN;
    float acc[2][8][4] = {};
    gemm_core(g_norm + (size_t)bm * Cc, g_wqkv + (size_t)bn * Cc, Cc, acc, As, Bs);
    EPILOGUE_COORDS;
    const float scale = 0.044194173824159216f;   // 1/sqrt(512)
    int seg = bn >> 9;                            // 0=q 1=k 2=v (tile inside segment)
    #pragma unroll
    for (int i = 0; i < 2; i++)
        #pragma unroll
        for (int half = 0; half < 2; half++) {
            int r = bm + wm * 32 + i * 16 + g + half * 8;
            #pragma unroll
            for (int j = 0; j < 8; j++) {
                int c = bn + wn * 64 + j * 8 + 2 * tg;
                float v0 = acc[i][j][half * 2 + 0] + b_qkv[c];
                float v1 = acc[i][j][half * 2 + 1] + b_qkv[c + 1];
                if (seg == 0) {
                    *(__nv_bfloat162*)(g_q + (size_t)r * Cc + c) =
                        __floats2bfloat162_rn(v0 * scale, v1 * scale);
                } else if (seg == 1) {
                    *(__nv_bfloat162*)(g_k + (size_t)r * Cc + (c - 512)) =
                        __floats2bfloat162_rn(v0, v1);
                } else {
                    int bb = r >> 10, sI = r & 1023;
                    g_vT[((size_t)(bb * Cc + (c - 1024))) * Ss + sI] = __float2bfloat16(v0);
                    g_vT[((size_t)(bb * Cc + (c - 1023))) * Ss + sI] = __float2bfloat16(v1);
                }
            }
        }
}

// QK^T: per batch [1024,1024] -> bf16 scores
__global__ void __launch_bounds__(256) qk_kernel() {
    GEMM_SMEM;
    int z = blockIdx.z;
    int bm = blockIdx.y * BM, bn = blockIdx.x * BN;
    float acc[2][8][4] = {};
    gemm_core(g_q + ((size_t)z * Ss + bm) * Cc,
              g_k + ((size_t)z * Ss + bn) * Cc, Cc, acc, As, Bs);
    EPILOGUE_COORDS;
    bf16* outp = g_scores + (size_t)z * Ss * Ss;
    #pragma unroll
    for (int i = 0; i < 2; i++)
        #pragma unroll
        for (int half = 0; half < 2; half++) {
            int r = bm + wm * 32 + i * 16 + g + half * 8;
            #pragma unroll
            for (int j = 0; j < 8; j++) {
                int c = bn + wn * 64 + j * 8 + 2 * tg;
                *(__nv_bfloat162*)(outp + (size_t)r * Ss + c) =
                    __floats2bfloat162_rn(acc[i][j][half * 2], acc[i][j][half * 2 + 1]);
            }
        }
}

// PV: per batch [1024,512] = probs[1024,1024] @ vT[512,1024]^T
__global__ void __launch_bounds__(256) pv_kernel() {
    GEMM_SMEM;
    int z = blockIdx.z;
    int bm = blockIdx.y * BM, bn = blockIdx.x * BN;
    float acc[2][8][4] = {};
    gemm_core(g_scores + (size_t)z * Ss * Ss + (size_t)bm * Ss,
              g_vT + ((size_t)z * Cc + bn) * Ss, Ss, acc, As, Bs);
    EPILOGUE_COORDS;
    #pragma unroll
    for (int i = 0; i < 2; i++)
        #pragma unroll
        for (int half = 0; half < 2; half++) {
            int r = bm + wm * 32 + i * 16 + g + half * 8;
            #pragma unroll
            for (int j = 0; j < 8; j++) {
                int c = bn + wn * 64 + j * 8 + 2 * tg;
                *(__nv_bfloat162*)(g_ao + ((size_t)z * Ss + r) * Cc + c) =
                    __floats2bfloat162_rn(acc[i][j][half * 2], acc[i][j][half * 2 + 1]);
            }
        }
}

// Out proj: per batch C[o=512,s=1024] = wout @ ao^T; + bias + residual -> fp32 out
__global__ void __launch_bounds__(256) out_kernel(
    const float* __restrict__ b_out, const float* __restrict__ x,
    float* __restrict__ out)
{
    GEMM_SMEM;
    int z = blockIdx.z;
    int bm = blockIdx.y * BM, bn = blockIdx.x * BN;
    float acc[2][8][4] = {};
    gemm_core(g_wout + (size_t)bm * Cc,
              g_ao + ((size_t)z * Ss + bn) * Cc, Cc, acc, As, Bs);
    EPILOGUE_COORDS;
    #pragma unroll
    for (int i = 0; i < 2; i++)
        #pragma unroll
        for (int half = 0; half < 2; half++) {
            int r = bm + wm * 32 + i * 16 + g + half * 8;   // channel o
            float bias = b_out[r];
            #pragma unroll
            for (int j = 0; j < 8; j++) {
                int c = bn + wn * 64 + j * 8 + 2 * tg;      // spatial s
                size_t off = ((size_t)(z * Cc + r)) * Ss + c;
                float2 xv = *(const float2*)(x + off);
                float2 ov;
                ov.x = acc[i][j][half * 2 + 0] + bias + xv.x;
                ov.y = acc[i][j][half * 2 + 1] + bias + xv.y;
                *(float2*)(out + off) = ov;
            }
        }
}

// ---------------- launcher ----------------
extern "C" void kernel_launch(void* const* d_in, const int* in_sizes, int n_in,
                              void* d_out, int out_size)
{
    const float* x     = (const float*)d_in[0];
    const float* gamma = (const float*)d_in[1];
    const float* beta  = (const float*)d_in[2];
    const float* w_qkv = (const float*)d_in[3];
    const float* b_qkv = (const float*)d_in[4];
    const float* w_out = (const float*)d_in[5];
    const float* b_out = (const float*)d_in[6];
    float* out = (float*)d_out;

    cvt_kernel<<<DIVUP(3 * Cc * Cc, 256), 256>>>(w_qkv, 3 * Cc * Cc, 0);
    cvt_kernel<<<DIVUP(Cc * Cc, 256), 256>>>(w_out, Cc * Cc, 1);
    groupnorm_kernel<<<Bn * GROUPS, 256>>>(x, gamma, beta);
    qkv_kernel<<<dim3(3 * Cc / BN, Bn * Ss / BM), 256>>>(b_qkv);
    qk_kernel<<<dim3(Ss / BN, Ss / BM, Bn), 256>>>();
    softmax_kernel<<<Bn * Ss, 256>>>();
    pv_kernel<<<dim3(Cc / BN, Ss / BM, Bn), 256>>>();
    out_kernel<<<dim3(Ss / BN, Cc / BM, Bn), 256>>>(b_out, x, out);
}